// round 1
// baseline (speedup 1.0000x reference)
#include <cuda_runtime.h>
#include <cuda_fp16.h>

#define B_ 256
#define P_ 2048
#define C_ 10
#define O_ 16
#define I_ 8
#define PT 4      // p-tile for u_hat kernel
#define PCH 64    // p-chunk per routing block

// u_hat stored as half2 pairs (o even, o odd), layout [p][c][b][o2]
// so that lane=b reads/writes 32 contiguous bytes (2x LDG.128 / STG.128).
__device__ __half2 g_uhat[(size_t)P_ * C_ * B_ * (O_ / 2)];
__device__ float g_s[B_ * C_ * O_];
__device__ float g_vsum[B_ * C_ * O_];

// ---------------------------------------------------------------------------
// Zero the s accumulator (atomics target).
// ---------------------------------------------------------------------------
__global__ void k_zero() {
    int i = blockIdx.x * blockDim.x + threadIdx.x;
    if (i < B_ * C_ * O_) g_s[i] = 0.f;
}

// ---------------------------------------------------------------------------
// K1: u_hat[b,p,c,o] = sum_i W[p,c,o,i] * u[b,p,i], stored fp16.
// Block = PT p's x all 256 b (thread = b). W tile staged in smem (broadcast
// reads across the warp are conflict-free).
// ---------------------------------------------------------------------------
__global__ void __launch_bounds__(256) k_uhat(const float* __restrict__ u,
                                              const float* __restrict__ W) {
    __shared__ float Ws[PT * C_ * O_ * I_];  // 5120 floats = 20 KB

    const int t = threadIdx.x;          // = b
    const int p0 = blockIdx.x * PT;

    // Cooperative, coalesced load of the W tile (PT*1280 floats).
    {
        const float4* Wg = (const float4*)(W + (size_t)p0 * C_ * O_ * I_);
        float4* Ws4 = (float4*)Ws;
#pragma unroll
        for (int k = 0; k < (PT * C_ * O_ * I_) / 4 / 256; k++)
            Ws4[t + k * 256] = Wg[t + k * 256];
    }

    // u[b, p0..p0+PT, 0..7] straight into registers.
    float ur[PT][I_];
    {
        const float4* ug = (const float4*)(u + ((size_t)t * P_ + p0) * I_);
#pragma unroll
        for (int p = 0; p < PT; p++) {
            float4 a = ug[p * 2 + 0];
            float4 b = ug[p * 2 + 1];
            ur[p][0] = a.x; ur[p][1] = a.y; ur[p][2] = a.z; ur[p][3] = a.w;
            ur[p][4] = b.x; ur[p][5] = b.y; ur[p][6] = b.z; ur[p][7] = b.w;
        }
    }
    __syncthreads();

#pragma unroll
    for (int p = 0; p < PT; p++) {
#pragma unroll
        for (int c = 0; c < C_; c++) {
            union { __half2 h[8]; uint4 q[2]; } ou;
#pragma unroll
            for (int o2 = 0; o2 < 8; o2++) {
                const float* w0 = Ws + ((p * C_ + c) * O_ + 2 * o2) * I_;
                float f0 = 0.f, f1 = 0.f;
#pragma unroll
                for (int i = 0; i < I_; i++) {
                    f0 = fmaf(w0[i],      ur[p][i], f0);
                    f1 = fmaf(w0[I_ + i], ur[p][i], f1);
                }
                ou.h[o2] = __floats2half2_rn(f0, f1);
            }
            uint4* dst = (uint4*)(g_uhat + ((((size_t)(p0 + p)) * C_ + c) * B_ + t) * 8);
            dst[0] = ou.q[0];
            dst[1] = ou.q[1];
        }
    }
}

// ---------------------------------------------------------------------------
// Routing pass: for each (b,p): logits[c] = u_hat[b,p,c,:] . vsum[b,c,:],
// cw = softmax_c(logits), s[b,c,o] += cw[c]*u_hat[b,p,c,o].
// warp = capsule c (10 warps), lane = b within a 32-b tile.
// UNIFORM=true => first iteration (softmax of zeros = 0.1), no smem/syncs.
// ---------------------------------------------------------------------------
template <bool UNIFORM>
__global__ void __launch_bounds__(320) k_route() {
    const int c = threadIdx.x >> 5;       // warp id = capsule
    const int lane = threadIdx.x & 31;    // b within tile
    const int b = blockIdx.y * 32 + lane;
    const int p0 = blockIdx.x * PCH;

    float vs[O_];
    if (!UNIFORM) {
        const float4* vp = (const float4*)(g_vsum + (b * C_ + c) * O_);
#pragma unroll
        for (int k = 0; k < 4; k++) {
            float4 v4 = vp[k];
            vs[4 * k + 0] = v4.x; vs[4 * k + 1] = v4.y;
            vs[4 * k + 2] = v4.z; vs[4 * k + 3] = v4.w;
        }
    }

    float sa[O_];
#pragma unroll
    for (int o = 0; o < O_; o++) sa[o] = 0.f;

    __shared__ float es[C_][32];

    for (int p = p0; p < p0 + PCH; p++) {
        const uint4* src = (const uint4*)(g_uhat + (((size_t)p * C_ + c) * B_ + b) * 8);
        union { uint4 q[2]; __half2 h[8]; } uu;
        uu.q[0] = src[0];
        uu.q[1] = src[1];
        float2 f[8];
#pragma unroll
        for (int k = 0; k < 8; k++) f[k] = __half22float2(uu.h[k]);

        float cw;
        if (UNIFORM) {
            cw = 0.1f;
        } else {
            // logit = u_hat . vsum  (|logit| <~ 2 over 3 iters => exp w/o max-sub is safe)
            float lg0 = 0.f, lg1 = 0.f;
#pragma unroll
            for (int k = 0; k < 8; k++) {
                lg0 = fmaf(f[k].x, vs[2 * k + 0], lg0);
                lg1 = fmaf(f[k].y, vs[2 * k + 1], lg1);
            }
            float e = __expf(lg0 + lg1);
            es[c][lane] = e;
            __syncthreads();
            float Z = 0.f;
#pragma unroll
            for (int cc = 0; cc < C_; cc++) Z += es[cc][lane];
            cw = e / Z;
            __syncthreads();
        }

#pragma unroll
        for (int k = 0; k < 8; k++) {
            sa[2 * k + 0] = fmaf(cw, f[k].x, sa[2 * k + 0]);
            sa[2 * k + 1] = fmaf(cw, f[k].y, sa[2 * k + 1]);
        }
    }

    float* sp = g_s + (b * C_ + c) * O_;
#pragma unroll
    for (int o = 0; o < O_; o++) atomicAdd(sp + o, sa[o]);
}

// ---------------------------------------------------------------------------
// Squash: v = (|s|^2/(1+|s|^2)) * s / sqrt(|s|^2 + 1e-9)
// MODE 0: vsum  = v, s = 0
// MODE 1: vsum += v, s = 0
// MODE 2: out   = v (final)
// block = one b, 160 threads = (c,o); norm reduced over 16-lane o-groups.
// ---------------------------------------------------------------------------
template <int MODE>
__global__ void __launch_bounds__(160) k_squash(float* __restrict__ out) {
    const int b = blockIdx.x;
    const int t = threadIdx.x;
    const int idx = b * (C_ * O_) + t;

    float sv = g_s[idx];
    float n2 = sv * sv;
#pragma unroll
    for (int d = 1; d < 16; d <<= 1) n2 += __shfl_xor_sync(0xffffffffu, n2, d);

    float scale = (n2 / (1.f + n2)) * rsqrtf(n2 + 1e-9f);
    float v = sv * scale;

    if (MODE == 0) {
        g_vsum[idx] = v;
        g_s[idx] = 0.f;
    } else if (MODE == 1) {
        g_vsum[idx] += v;
        g_s[idx] = 0.f;
    } else {
        out[idx] = v;
    }
}

// ---------------------------------------------------------------------------
extern "C" void kernel_launch(void* const* d_in, const int* in_sizes, int n_in,
                              void* d_out, int out_size) {
    const float* u = (const float*)d_in[0];
    const float* W = (const float*)d_in[1];
    // Robustness: identify by size in case of ordering surprises.
    if (n_in >= 2 && in_sizes[0] == P_ * C_ * O_ * I_ && in_sizes[1] == B_ * P_ * I_) {
        const float* tmp = u; u = W; W = tmp;
    }
    float* out = (float*)d_out;

    dim3 rg(P_ / PCH, B_ / 32);  // (32, 8) = 256 blocks

    k_zero<<<(B_ * C_ * O_ + 1023) / 1024, 1024>>>();
    k_uhat<<<P_ / PT, 256>>>(u, W);

    k_route<true><<<rg, 320>>>();          // iter 1 (uniform weights)
    k_squash<0><<<B_, 160>>>(out);         // v1 -> vsum, zero s

    k_route<false><<<rg, 320>>>();         // iter 2
    k_squash<1><<<B_, 160>>>(out);         // vsum += v2, zero s

    k_route<false><<<rg, 320>>>();         // iter 3
    k_squash<2><<<B_, 160>>>(out);         // final v -> d_out
}

// round 2
// speedup vs baseline: 1.0075x; 1.0075x over previous
#include <cuda_runtime.h>
#include <cuda_fp16.h>

#define B_ 256
#define P_ 2048
#define C_ 10
#define O_ 16
#define I_ 8
#define PT 4      // p-tile for u_hat kernel
#define PCH 64    // p-chunk per routing block
#define RB 8      // p's per barrier round in routing

// u_hat as half2 pairs (o even, o odd), layout [p][c][b][o2]:
// lane=b reads/writes 32 contiguous bytes (2x LDG.128 / STG.128).
__device__ __align__(16) __half2 g_uhat[(size_t)P_ * C_ * B_ * (O_ / 2)];
__device__ __align__(16) float g_s[B_ * C_ * O_];      // zero-init; invariant: 0 at entry
__device__ __align__(16) float g_vsum[B_ * C_ * O_];

// ---------------------------------------------------------------------------
// packed f32x2 helpers
// ---------------------------------------------------------------------------
typedef unsigned long long ull;

__device__ __forceinline__ ull ffma2(ull a, ull b, ull c) {
    ull d;
    asm("fma.rn.f32x2 %0, %1, %2, %3;" : "=l"(d) : "l"(a), "l"(b), "l"(c));
    return d;
}
__device__ __forceinline__ ull pack2(float x, float y) {
    ull r;
    asm("mov.b64 %0, {%1, %2};" : "=l"(r) : "f"(x), "f"(y));
    return r;
}
__device__ __forceinline__ float2 unpack2(ull a) {
    float2 f;
    asm("mov.b64 {%0, %1}, %2;" : "=f"(f.x), "=f"(f.y) : "l"(a));
    return f;
}
__device__ __forceinline__ float rcp_fast(float x) {
    float r;
    asm("rcp.approx.f32 %0, %1;" : "=f"(r) : "f"(x));
    return r;
}

// ---------------------------------------------------------------------------
// K1: u_hat[b,p,c,o] = sum_i W[p,c,o,i]*u[b,p,i], stored fp16.
// W tile transposed in smem to [p][c][i][o] so o-adjacent pairs share the
// u[i] multiplier -> packed fma.rn.f32x2 (half the FMA issue).
// ---------------------------------------------------------------------------
__global__ void __launch_bounds__(256) k_uhat(const float* __restrict__ u,
                                              const float* __restrict__ W) {
    __shared__ float Ws[PT * C_ * I_ * O_];  // [pc][i][o], 5120 floats = 20KB

    const int t = threadIdx.x;          // = b
    const int p0 = blockIdx.x * PT;

    // Cooperative load + transpose of the W tile.
    {
        const float4* Wg = (const float4*)(W + (size_t)p0 * C_ * O_ * I_);
#pragma unroll
        for (int k = 0; k < (PT * C_ * O_ * I_) / 4 / 256; k++) {
            float4 w4 = Wg[t + k * 256];
            int L = (t + k * 256) * 4;      // element index in [pc][o][i]
            int i = L & 7;                   // 0 or 4
            int o = (L >> 3) & 15;
            int pc = L >> 7;
            float* dst = Ws + (pc * I_) * O_ + o;
            dst[(i + 0) * O_] = w4.x;
            dst[(i + 1) * O_] = w4.y;
            dst[(i + 2) * O_] = w4.z;
            dst[(i + 3) * O_] = w4.w;
        }
    }

    // u[b, p0..p0+PT, 0..7] into registers (32B contiguous per (b,p)).
    float ur[PT][I_];
    {
        const float4* ug = (const float4*)(u + ((size_t)t * P_ + p0) * I_);
#pragma unroll
        for (int p = 0; p < PT; p++) {
            float4 a = ug[p * 2 + 0];
            float4 b = ug[p * 2 + 1];
            ur[p][0] = a.x; ur[p][1] = a.y; ur[p][2] = a.z; ur[p][3] = a.w;
            ur[p][4] = b.x; ur[p][5] = b.y; ur[p][6] = b.z; ur[p][7] = b.w;
        }
    }
    __syncthreads();

#pragma unroll
    for (int p = 0; p < PT; p++) {
        ull uu[I_];
#pragma unroll
        for (int i = 0; i < I_; i++) uu[i] = pack2(ur[p][i], ur[p][i]);

#pragma unroll 1
        for (int c = 0; c < C_; c++) {
            const ulonglong2* w2 = (const ulonglong2*)(Ws + (p * C_ + c) * I_ * O_);
            ull a[8];
#pragma unroll
            for (int k = 0; k < 8; k++) a[k] = 0ULL;
#pragma unroll
            for (int i = 0; i < I_; i++) {
                ulonglong2 q0 = w2[i * 4 + 0];
                ulonglong2 q1 = w2[i * 4 + 1];
                ulonglong2 q2 = w2[i * 4 + 2];
                ulonglong2 q3 = w2[i * 4 + 3];
                a[0] = ffma2(q0.x, uu[i], a[0]);
                a[1] = ffma2(q0.y, uu[i], a[1]);
                a[2] = ffma2(q1.x, uu[i], a[2]);
                a[3] = ffma2(q1.y, uu[i], a[3]);
                a[4] = ffma2(q2.x, uu[i], a[4]);
                a[5] = ffma2(q2.y, uu[i], a[5]);
                a[6] = ffma2(q3.x, uu[i], a[6]);
                a[7] = ffma2(q3.y, uu[i], a[7]);
            }
            union { __half2 h[8]; uint4 q[2]; } ou;
#pragma unroll
            for (int k = 0; k < 8; k++) {
                float2 f = unpack2(a[k]);
                ou.h[k] = __floats2half2_rn(f.x, f.y);
            }
            uint4* dst = (uint4*)(g_uhat + ((((size_t)(p0 + p)) * C_ + c) * B_ + t) * 8);
            dst[0] = ou.q[0];
            dst[1] = ou.q[1];
        }
    }
}

// ---------------------------------------------------------------------------
// Routing pass. warp = capsule c (10 warps), lane = b within a 32-b tile.
// Rounds of RB=8 p's: (1) front-batched loads + HFMA2 logits + exp -> smem,
// (2) barrier, warps 0..RB-1 each reduce one p's Z over c and store rcp(Z),
// (3) barrier, all lanes re-read the tile (L1/L2 hit) and accumulate with
// packed f32x2 FMA. UNIFORM=true => iter 1 (softmax(0)=0.1), pure stream.
// ---------------------------------------------------------------------------
template <bool UNIFORM>
__global__ void __launch_bounds__(320) k_route() {
    const int c = threadIdx.x >> 5;
    const int lane = threadIdx.x & 31;
    const int b = blockIdx.y * 32 + lane;
    const int p0 = blockIdx.x * PCH;

    __shared__ float es[RB][C_][32];
    __shared__ float rz[RB][32];

    __half2 vsh[8];
    if (!UNIFORM) {
        const float4* vp = (const float4*)(g_vsum + (b * C_ + c) * O_);
#pragma unroll
        for (int k = 0; k < 4; k++) {
            float4 v4 = vp[k];
            vsh[2 * k + 0] = __floats2half2_rn(v4.x, v4.y);
            vsh[2 * k + 1] = __floats2half2_rn(v4.z, v4.w);
        }
    }

    ull acc[8];
#pragma unroll
    for (int k = 0; k < 8; k++) acc[k] = 0ULL;

#pragma unroll 1
    for (int r = 0; r < PCH / RB; r++) {
        const int pb = p0 + r * RB;

        if (UNIFORM) {
            const ull cw2 = pack2(0.1f, 0.1f);
#pragma unroll
            for (int j = 0; j < RB; j++) {
                const uint4* src =
                    (const uint4*)(g_uhat + (((size_t)(pb + j) * C_ + c) * B_ + b) * 8);
                union { uint4 q[2]; __half2 h[8]; } uu;
                uu.q[0] = src[0];
                uu.q[1] = src[1];
#pragma unroll
                for (int k = 0; k < 8; k++) {
                    float2 f = __half22float2(uu.h[k]);
                    acc[k] = ffma2(cw2, pack2(f.x, f.y), acc[k]);
                }
            }
        } else {
            float e[RB];
            // Phase 1: logits + exp (loads front-batched by the unroll).
#pragma unroll
            for (int j = 0; j < RB; j++) {
                const uint4* src =
                    (const uint4*)(g_uhat + (((size_t)(pb + j) * C_ + c) * B_ + b) * 8);
                union { uint4 q[2]; __half2 h[8]; } uu;
                uu.q[0] = src[0];
                uu.q[1] = src[1];
                __half2 lg = __floats2half2_rn(0.f, 0.f);
#pragma unroll
                for (int k = 0; k < 8; k++) lg = __hfma2(uu.h[k], vsh[k], lg);
                float l = __low2float(lg) + __high2float(lg);
                e[j] = __expf(l);   // |logit| small: no max-subtraction needed
                es[j][c][lane] = e[j];
            }
            __syncthreads();
            // Phase 2: one warp per p computes 1/Z.
            if (c < RB) {
                float Z = 0.f;
#pragma unroll
                for (int cc = 0; cc < C_; cc++) Z += es[c][cc][lane];
                rz[c][lane] = rcp_fast(Z);
            }
            __syncthreads();
            // Phase 3: weighted accumulate (reload tile: L1/L2 resident).
#pragma unroll
            for (int j = 0; j < RB; j++) {
                const uint4* src =
                    (const uint4*)(g_uhat + (((size_t)(pb + j) * C_ + c) * B_ + b) * 8);
                union { uint4 q[2]; __half2 h[8]; } uu;
                uu.q[0] = src[0];
                uu.q[1] = src[1];
                float cw = e[j] * rz[j][lane];
                ull cw2 = pack2(cw, cw);
#pragma unroll
                for (int k = 0; k < 8; k++) {
                    float2 f = __half22float2(uu.h[k]);
                    acc[k] = ffma2(cw2, pack2(f.x, f.y), acc[k]);
                }
            }
        }
    }

    float* sp = g_s + (b * C_ + c) * O_;
#pragma unroll
    for (int k = 0; k < 8; k++) {
        float2 f = unpack2(acc[k]);
        atomicAdd(sp + 2 * k + 0, f.x);
        atomicAdd(sp + 2 * k + 1, f.y);
    }
}

// ---------------------------------------------------------------------------
// Squash. MODE 0: vsum=v, s=0.  MODE 1: vsum+=v, s=0.  MODE 2: out=v, s=0.
// (s re-zeroed every time keeps the s==0 entry invariant across graph replays.)
// 640 threads = 4 b's; 16-lane shuffle groups align with o-vectors.
// ---------------------------------------------------------------------------
template <int MODE>
__global__ void __launch_bounds__(640) k_squash(float* __restrict__ out) {
    const int idx = blockIdx.x * 640 + threadIdx.x;

    float sv = g_s[idx];
    float n2 = sv * sv;
#pragma unroll
    for (int d = 1; d < 16; d <<= 1) n2 += __shfl_xor_sync(0xffffffffu, n2, d);

    float scale = (n2 / (1.f + n2)) * rsqrtf(n2 + 1e-9f);
    float v = sv * scale;

    g_s[idx] = 0.f;
    if (MODE == 0) {
        g_vsum[idx] = v;
    } else if (MODE == 1) {
        g_vsum[idx] += v;
    } else {
        out[idx] = v;
    }
}

// ---------------------------------------------------------------------------
extern "C" void kernel_launch(void* const* d_in, const int* in_sizes, int n_in,
                              void* d_out, int out_size) {
    const float* u = (const float*)d_in[0];
    const float* W = (const float*)d_in[1];
    if (n_in >= 2 && in_sizes[0] == P_ * C_ * O_ * I_ && in_sizes[1] == B_ * P_ * I_) {
        const float* tmp = u; u = W; W = tmp;
    }
    float* out = (float*)d_out;

    dim3 rg(P_ / PCH, B_ / 32);  // (32, 8) = 256 blocks

    k_uhat<<<P_ / PT, 256>>>(u, W);

    k_route<true><<<rg, 320>>>();                       // iter 1 (uniform)
    k_squash<0><<<(B_ * C_ * O_) / 640, 640>>>(out);    // v1 -> vsum, s=0

    k_route<false><<<rg, 320>>>();                      // iter 2
    k_squash<1><<<(B_ * C_ * O_) / 640, 640>>>(out);    // vsum += v2, s=0

    k_route<false><<<rg, 320>>>();                      // iter 3
    k_squash<2><<<(B_ * C_ * O_) / 640, 640>>>(out);    // out = v3, s=0
}